// round 4
// baseline (speedup 1.0000x reference)
#include <cuda_runtime.h>
#include <math.h>

#define BB 8192
#define LL 64
#define VV 28
#define LATENT 32
#define PAD_TOKEN 26
#define EOS_TOKEN 27
#define EPSF 1e-7f
#define NSLOTS 128

// Cross-block accumulators (zeroed by init kernel each launch).
__device__ double g_letter[NSLOTS][VV];
__device__ double g_scal[NSLOTS][8];

__constant__ float c_freq[VV] = {
    0.0817f, 0.0149f, 0.0278f, 0.0425f, 0.127f,  0.0223f, 0.0202f,
    0.0609f, 0.0697f, 0.0015f, 0.0077f, 0.0403f, 0.0241f, 0.0675f,
    0.0751f, 0.0193f, 0.001f,  0.0599f, 0.0633f, 0.0906f, 0.0276f,
    0.0098f, 0.0236f, 0.0015f, 0.0197f, 0.0007f, 0.0f,    0.0f};

__global__ void vae_init_kernel() {
    int i = blockIdx.x * blockDim.x + threadIdx.x;
    int stride = gridDim.x * blockDim.x;
    double* pl = &g_letter[0][0];
    for (int j = i; j < NSLOTS * VV; j += stride) pl[j] = 0.0;
    double* ps = &g_scal[0][0];
    for (int j = i; j < NSLOTS * 8; j += stride) ps[j] = 0.0;
}

__device__ __forceinline__ double wred(double v) {
#pragma unroll
    for (int o = 16; o > 0; o >>= 1)
        v += __shfl_down_sync(0xffffffffu, v, o);
    return v;
}

__global__ __launch_bounds__(256) void vae_main_kernel(
    const float* __restrict__ x,
    const float* __restrict__ rec,
    const float* __restrict__ zm,
    const float* __restrict__ zlv,
    const float* __restrict__ cls) {
    __shared__ float sx[LL * VV];
    __shared__ float sr[LL * VV];
    __shared__ int   stgt[LL];
    __shared__ float smexp[LL];
    __shared__ float sadj[LL - 1];
    __shared__ float swpow[LL];

    const int b = blockIdx.x;
    const int tid = threadIdx.x;
    const int slot = b & (NSLOTS - 1);

    // Coalesced float4 load of this row of x and reconstruction.
    // Row stride = 64*28 floats = 7168 bytes (16B aligned).
    {
        const float4* gx = (const float4*)(x + (size_t)b * (LL * VV));
        const float4* gr = (const float4*)(rec + (size_t)b * (LL * VV));
        float4* s4x = (float4*)sx;
        float4* s4r = (float4*)sr;
#pragma unroll
        for (int i = tid; i < (LL * VV) / 4; i += 256) {
            s4x[i] = gx[i];
            s4r[i] = gr[i];
        }
    }
    if (tid < LL) swpow[tid] = powf((float)tid, 2.5f);  // swpow[m] = m^2.5
    __syncthreads();

    float v_rec = 0.f, v_maskcnt = 0.f, v_mexp = 0.f;
    if (tid < LL) {
        const float* xr = sx + tid * VV;
        int am = 0;
        float bv = xr[0];
#pragma unroll
        for (int v = 1; v < VV; v++) {
            float xv = xr[v];
            if (xv > bv) { bv = xv; am = v; }  // first-max semantics like jnp.argmax
        }
        stgt[tid] = am;
        float m  = (am != PAD_TOKEN) ? 1.f : 0.f;
        float me = (am != PAD_TOKEN && am != EOS_TOKEN) ? 1.f : 0.f;
        smexp[tid] = me;
        float p = sr[tid * VV + am];
        p = fminf(fmaxf(p, EPSF), 1.f);
        v_rec = -m * logf(p);
        v_maskcnt = m;
        v_mexp = me;
    }
    __syncthreads();

    // adjacent[j] = dot(rec[j+1], rec[j]) * (tgt[j+1] != PAD)
    if (tid < LL - 1) {
        const float* a = sr + tid * VV;
        const float* c = sr + (tid + 1) * VV;
        float d = 0.f;
#pragma unroll
        for (int v = 0; v < VV; v++) d += a[v] * c[v];
        float mm = (stgt[tid + 1] != PAD_TOKEN) ? 1.f : 0.f;
        sadj[tid] = d * mm;
    }
    __syncthreads();

    // Consecutive similarity: per start-index running window product.
    // acc = sum_m m^2.5 * prod(adjacent[j .. j+m-1]); zero product => all
    // remaining terms zero (mask or underflow), so early exit is exact.
    float v_consec = 0.f;
    if (tid < LL - 1) {
        float p = sadj[tid];
        v_consec = p;  // m = 1, weight 1
        for (int k = 1; k < LL - 1; k++) {
            if (tid + k >= LL - 1 || p == 0.f) break;
            p *= sadj[tid + k];
            v_consec += swpow[k + 1] * p;
        }
    }

    // Per-letter masked probability sums (warp 0, conflict-free SMEM reads).
    if (tid < VV) {
        double ls = 0.0;
#pragma unroll 8
        for (int l = 0; l < LL; l++)
            ls += (double)(sr[l * VV + tid] * smexp[l]);
        atomicAdd(&g_letter[slot][tid], ls);
    }

    // KL terms: 32 latents for this batch row.
    float v_kl = 0.f;
    if (tid < LATENT) {
        float m  = zm[(size_t)b * LATENT + tid];
        float lv = zlv[(size_t)b * LATENT + tid];
        v_kl = 1.f + lv - m * m - expf(lv);
    }
    float v_cls = (tid == 0) ? logf(cls[b] + EPSF) : 0.f;

    // Warp-level reductions (only warps 0 and 1 carry nonzero values).
    int warp = tid >> 5;
    if (warp < 2) {
        double r0 = wred((double)v_rec);
        double r1 = wred((double)v_maskcnt);
        double r2 = wred((double)v_mexp);
        double r3 = wred((double)v_consec);
        double r4 = (warp == 0) ? wred((double)v_kl) : 0.0;
        double r5 = (warp == 0) ? wred((double)v_cls) : 0.0;
        if ((tid & 31) == 0) {
            double* s = g_scal[slot];
            atomicAdd(s + 0, r0);
            atomicAdd(s + 1, r1);
            atomicAdd(s + 2, r2);
            atomicAdd(s + 3, r3);
            if (warp == 0) {
                atomicAdd(s + 4, r4);
                atomicAdd(s + 5, r5);
            }
        }
    }
}

__global__ void vae_finalize_kernel(float* __restrict__ out) {
    __shared__ double sl[VV];
    __shared__ double ss[6];
    int tid = threadIdx.x;
    if (tid < VV) {
        double s = 0.0;
        for (int k = 0; k < NSLOTS; k++) s += g_letter[k][tid];
        sl[tid] = s;
    }
    if (tid >= 32 && tid < 38) {
        int j = tid - 32;
        double s = 0.0;
        for (int k = 0; k < NSLOTS; k++) s += g_scal[k][j];
        ss[j] = s;
    }
    __syncthreads();
    if (tid == 0) {
        double rec_loss = ss[0] / ss[1];
        double kl_loss  = -0.5 * ss[4] / (double)(BB * LATENT);
        double cls_loss = -ss[5] / (double)BB;
        double inv_me = 1.0 / ss[2];
        double fp = 0.0;
        for (int v = 0; v < VV; v++) {
            double d = sl[v] * inv_me - (double)c_freq[v];
            if (d > 0.0) fp += d;
        }
        double total = rec_loss + 0.1 * kl_loss + 2.0 * cls_loss +
                       0.2 * ss[3] + 0.5 * fp;
        out[0] = (float)total;
    }
}

extern "C" void kernel_launch(void* const* d_in, const int* in_sizes, int n_in,
                              void* d_out, int out_size) {
    (void)in_sizes; (void)n_in; (void)out_size;
    const float* x   = (const float*)d_in[0];
    const float* rec = (const float*)d_in[1];
    const float* zm  = (const float*)d_in[2];
    const float* zlv = (const float*)d_in[3];
    const float* cls = (const float*)d_in[4];

    vae_init_kernel<<<8, 256>>>();
    vae_main_kernel<<<BB, 256>>>(x, rec, zm, zlv, cls);
    vae_finalize_kernel<<<1, 64>>>((float*)d_out);
}

// round 5
// speedup vs baseline: 3.1934x; 3.1934x over previous
#include <cuda_runtime.h>
#include <math.h>

#define BB 8192
#define LL 64
#define VV 28
#define PADV 29            // smem row stride (29 coprime with 32 -> conflict-free)
#define LATENT 32
#define PAD_TOKEN 26
#define EOS_TOKEN 27
#define EPSF 1e-7f
#define NSLOTS 128
#define RPB 2              // rows per block
#define TPB 128
#define NGRID (BB / RPB)   // 4096

// Cross-block accumulators. Statically zero; finalize kernel re-zeroes them
// after consuming, so every kernel_launch call starts from zero (deterministic).
__device__ float g_letter[NSLOTS][VV];
__device__ float g_scal[NSLOTS][8];

__constant__ float c_freq[VV] = {
    0.0817f, 0.0149f, 0.0278f, 0.0425f, 0.127f,  0.0223f, 0.0202f,
    0.0609f, 0.0697f, 0.0015f, 0.0077f, 0.0403f, 0.0241f, 0.0675f,
    0.0751f, 0.0193f, 0.001f,  0.0599f, 0.0633f, 0.0906f, 0.0276f,
    0.0098f, 0.0236f, 0.0015f, 0.0197f, 0.0007f, 0.0f,    0.0f};

__device__ __forceinline__ float wredf(float v) {
#pragma unroll
    for (int o = 16; o > 0; o >>= 1)
        v += __shfl_down_sync(0xffffffffu, v, o);
    return v;
}

__global__ void __launch_bounds__(TPB) vae_main(
    const float* __restrict__ x,
    const float* __restrict__ rec,
    const float* __restrict__ zm,
    const float* __restrict__ zlv,
    const float* __restrict__ cls) {
    __shared__ float sr[RPB][LL * PADV];   // padded rec rows
    __shared__ float sadj[RPB][LL];        // adjacent dots (63 used)
    __shared__ int   stgt[RPB][LL];
    __shared__ float smexp[RPB][LL];
    __shared__ float swpow[LL];            // m^2.5
    __shared__ float spart[RPB][VV];       // letter partial (upper half)
    __shared__ float sred[6][TPB / 32];

    const int tid  = threadIdx.x;
    const int b0   = blockIdx.x * RPB;
    const int slot = blockIdx.x & (NSLOTS - 1);
    const int row  = tid >> 6;             // 0..1
    const int pos  = tid & 63;
    const int warp = tid >> 5;
    const int lane = tid & 31;

    // --- early independent global loads (KL / classifier) ---
    float zmv = 0.f, zlvv = 0.f;
    if (tid < RPB * LATENT) {
        zmv  = zm[(size_t)b0 * LATENT + tid];   // fully coalesced 64 floats
        zlvv = zlv[(size_t)b0 * LATENT + tid];
    }
    float clsv = 0.f;
    if (tid >= 64 && tid < 64 + RPB) clsv = cls[b0 + (tid - 64)];

    // --- stage rec rows into padded smem (coalesced float4 global reads) ---
    {
        const float4* gr = (const float4*)(rec + (size_t)b0 * (LL * VV));
#pragma unroll
        for (int j = 0; j < (RPB * LL * VV / 4) / TPB; j++) {   // 7 iters
            int i = tid + j * TPB;
            float4 v = gr[i];
            int r   = i / (LL * VV / 4);
            int rem = i - r * (LL * VV / 4);
            int p   = rem / 7;
            int c   = rem - p * 7;
            float* d = &sr[r][p * PADV + c * 4];
            d[0] = v.x; d[1] = v.y; d[2] = v.z; d[3] = v.w;
        }
    }

    // --- argmax of x for this thread's position, direct from global ---
    // lane footprint: 112 contiguous bytes, warp footprint contiguous & fully used
    int am = 0;
    {
        const float4* gx = (const float4*)(x + (size_t)(b0 + row) * (LL * VV) + pos * VV);
        float bv = -INFINITY;
#pragma unroll
        for (int c = 0; c < 7; c++) {
            float4 v = gx[c];
            if (v.x > bv) { bv = v.x; am = c * 4 + 0; }
            if (v.y > bv) { bv = v.y; am = c * 4 + 1; }
            if (v.z > bv) { bv = v.z; am = c * 4 + 2; }
            if (v.w > bv) { bv = v.w; am = c * 4 + 3; }
        }
    }
    stgt[row][pos] = am;
    const float m  = (am != PAD_TOKEN) ? 1.f : 0.f;
    const float me = (am != PAD_TOKEN && am != EOS_TOKEN) ? 1.f : 0.f;
    smexp[row][pos] = me;
    if (tid < LL) swpow[tid] = powf((float)tid, 2.5f);
    __syncthreads();

    // --- reconstruction CE (clip + log on target prob) ---
    float pt = sr[row][pos * PADV + am];
    pt = fminf(fmaxf(pt, EPSF), 1.f);
    float v_rec = -m * __logf(pt);

    // --- adjacent[j] = dot(rec[j], rec[j+1]) * (tgt[j+1] != PAD) ---
    float adjv = 0.f;
    if (pos < LL - 1) {
        const float* a  = &sr[row][pos * PADV];
        const float* c2 = a + PADV;
        float d0 = 0.f, d1 = 0.f;
#pragma unroll
        for (int v = 0; v < VV; v += 2) {
            d0 += a[v] * c2[v];
            d1 += a[v + 1] * c2[v + 1];
        }
        float mm = (stgt[row][pos + 1] != PAD_TOKEN) ? 1.f : 0.f;
        adjv = (d0 + d1) * mm;
    }
    sadj[row][pos] = adjv;   // pos==63 writes 0 (never read)
    __syncthreads();

    // --- consecutive similarity: running window product, early exit on 0 ---
    // product of softmax-dot values underflows/masks to exact 0 quickly, after
    // which all remaining terms are exactly 0 -> break is exact.
    float v_consec = 0.f;
    if (pos < LL - 1) {
        const float* aj = sadj[row];
        float p = aj[pos];
        v_consec = p;                 // m=1, weight 1
        const int rem = 62 - pos;     // k ranges 1..rem
        int k = 1;
        while (k + 3 <= rem) {
            if (p == 0.f) break;
            float a0 = aj[pos + k], a1 = aj[pos + k + 1];
            float a2 = aj[pos + k + 2], a3 = aj[pos + k + 3];
            p *= a0; v_consec += swpow[k + 1] * p;
            p *= a1; v_consec += swpow[k + 2] * p;
            p *= a2; v_consec += swpow[k + 3] * p;
            p *= a3; v_consec += swpow[k + 4] * p;
            k += 4;
        }
        while (k <= rem && p != 0.f) {
            p *= aj[pos + k];
            v_consec += swpow[k + 1] * p;
            k++;
        }
    }

    // --- per-letter masked sums: 56 threads/row, 32 FMAs each ---
    const int half   = (pos >= 32) ? 1 : 0;
    const int letter = pos - half * 32;
    float ls = 0.f;
    if (letter < VV) {
        const float* base = &sr[row][half * 32 * PADV + letter];
        const float* mex  = &smexp[row][half * 32];
#pragma unroll
        for (int l = 0; l < 32; l++) ls += base[l * PADV] * mex[l];
        if (half) spart[row][letter] = ls;
    }

    // --- KL + classifier terms ---
    float v_kl  = (tid < RPB * LATENT) ? (1.f + zlvv - zmv * zmv - __expf(zlvv)) : 0.f;
    float v_cls = (tid >= 64 && tid < 64 + RPB) ? __logf(clsv + EPSF) : 0.f;

    // --- block reduction (float) ---
    float r0 = wredf(v_rec);
    float r1 = wredf(m);
    float r2 = wredf(me);
    float r3 = wredf(v_consec);
    float r4 = wredf(v_kl);
    float r5 = wredf(v_cls);
    if (lane == 0) {
        sred[0][warp] = r0; sred[1][warp] = r1; sred[2][warp] = r2;
        sred[3][warp] = r3; sred[4][warp] = r4; sred[5][warp] = r5;
    }
    __syncthreads();

    if (!half && letter < VV)
        atomicAdd(&g_letter[slot][letter], ls + spart[row][letter]);

    if (tid < 6) {
        float s = sred[tid][0] + sred[tid][1] + sred[tid][2] + sred[tid][3];
        atomicAdd(&g_scal[slot][tid], s);
    }
}

__global__ void __launch_bounds__(256) vae_finalize(float* __restrict__ out) {
    __shared__ float sl[VV];
    __shared__ double ss[6];
    const int tid  = threadIdx.x;
    const int warp = tid >> 5;
    const int lane = tid & 31;

    if (tid < VV) sl[tid] = 0.f;
    __syncthreads();

    // letters: 8 warps, each sums 16 slots for its lane's letter
    if (lane < VV) {
        float s = 0.f;
        int k0 = warp * (NSLOTS / 8);
#pragma unroll
        for (int k = 0; k < NSLOTS / 8; k++) s += g_letter[k0 + k][lane];
        atomicAdd(&sl[lane], s);
    }
    // scalars: warps 0..5, warp q sums quantity q across 128 slots
    if (warp < 6) {
        float s = 0.f;
#pragma unroll
        for (int k = 0; k < NSLOTS / 32; k++) s += g_scal[lane + k * 32][warp];
#pragma unroll
        for (int o = 16; o > 0; o >>= 1) s += __shfl_down_sync(0xffffffffu, s, o);
        if (lane == 0) ss[warp] = (double)s;
    }
    __syncthreads();

    // re-zero accumulators for the next call (all blocks done; same launch)
    {
        float* pl = &g_letter[0][0];
        for (int j = tid; j < NSLOTS * VV; j += 256) pl[j] = 0.f;
        float* psc = &g_scal[0][0];
        for (int j = tid; j < NSLOTS * 8; j += 256) psc[j] = 0.f;
    }

    if (tid == 0) {
        double rec_loss = ss[0] / ss[1];
        double kl_loss  = -0.5 * ss[4] / (double)(BB * LATENT);
        double cls_loss = -ss[5] / (double)BB;
        double inv_me   = 1.0 / ss[2];
        double fp = 0.0;
        for (int v = 0; v < VV; v++) {
            double d = (double)sl[v] * inv_me - (double)c_freq[v];
            if (d > 0.0) fp += d;
        }
        double total = rec_loss + 0.1 * kl_loss + 2.0 * cls_loss +
                       0.2 * ss[3] + 0.5 * fp;
        out[0] = (float)total;
    }
}

extern "C" void kernel_launch(void* const* d_in, const int* in_sizes, int n_in,
                              void* d_out, int out_size) {
    (void)in_sizes; (void)n_in; (void)out_size;
    const float* x   = (const float*)d_in[0];
    const float* rec = (const float*)d_in[1];
    const float* zm  = (const float*)d_in[2];
    const float* zlv = (const float*)d_in[3];
    const float* cls = (const float*)d_in[4];

    vae_main<<<NGRID, TPB>>>(x, rec, zm, zlv, cls);
    vae_finalize<<<1, 256>>>((float*)d_out);
}